// round 3
// baseline (speedup 1.0000x reference)
#include <cuda_runtime.h>
#include <cstdint>

#define BB 2
#define NN 8192
#define CC 80
#define NW 128  /* 64-bit words per mask row = NN/64 */

typedef unsigned long long u64;
typedef unsigned int u32;

/* output layout (concatenated flat float32, tuple order) */
#define OFF_BOXES 0
#define OFF_MS    (BB*NN*4)
#define OFF_LB    (OFF_MS + BB*NN)
#define OFF_KEEP  (OFF_LB + BB*NN)
#define OFF_ALL   (OFF_KEEP + BB*NN)

/* static device scratch (no allocation allowed) */
__device__ u64 g_maskT[BB][NW][NN];   /* 16 MB, TRANSPOSED: [batch][word][row] */
__device__ u64 g_diagT[BB][NW][64];   /* transposed 64x64 diagonal tiles */
__device__ u64 g_keys[BB][NN];
__device__ u32 g_sorted[BB][NN];
__device__ int g_valid[BB][NN];

/* ------------------------------------------------------------------ */
/* Kernel 1: sigmoid / max / argmax / box decode / valid / sort keys   */
__global__ void prep_kernel(const float* __restrict__ logits,
                            const float* __restrict__ deltas,
                            const float* __restrict__ anchors,
                            float* __restrict__ out)
{
    int wid  = (blockIdx.x * blockDim.x + threadIdx.x) >> 5;
    int lane = threadIdx.x & 31;
    if (wid >= BB * NN) return;
    int b = wid / NN, n = wid % NN;

    const float* lg = logits + (size_t)wid * CC;
    float* as_out   = out + OFF_ALL + (size_t)wid * CC;

    float v0 = lg[lane];
    float v1 = lg[lane + 32];
    float v2 = (lane < 16) ? lg[lane + 64] : -INFINITY;

    as_out[lane]      = 1.0f / (1.0f + expf(-v0));
    as_out[lane + 32] = 1.0f / (1.0f + expf(-v1));
    if (lane < 16) as_out[lane + 64] = 1.0f / (1.0f + expf(-v2));

    float mv = v0; int mi = lane;
    if (v1 > mv) { mv = v1; mi = lane + 32; }
    if (v2 > mv) { mv = v2; mi = lane + 64; }

    for (int off = 16; off; off >>= 1) {
        float ov = __shfl_down_sync(0xffffffffu, mv, off);
        int   oi = __shfl_down_sync(0xffffffffu, mi, off);
        if (ov > mv || (ov == mv && oi < mi)) { mv = ov; mi = oi; }
    }

    if (lane == 0) {
        float ms = 1.0f / (1.0f + expf(-mv));
        out[OFF_MS + wid] = ms;
        out[OFF_LB + wid] = (float)mi;

        const float* dl = deltas  + (size_t)wid * 4;
        const float* an = anchors + (size_t)n * 4;
        float a0 = an[0], a1 = an[1], a2 = an[2], a3 = an[3];
        float aw = a2 - a0, ah = a3 - a1;
        float acx = a0 + 0.5f * aw, acy = a1 + 0.5f * ah;
        float dx = dl[0], dy = dl[1];
        float dw = fminf(dl[2], 4.0f), dh = fminf(dl[3], 4.0f);
        float pcx = dx * aw + acx, pcy = dy * ah + acy;
        float pw = expf(dw) * aw, ph = expf(dh) * ah;
        float x1 = fminf(fmaxf(pcx - 0.5f * pw, 0.0f), 1.0f);
        float y1 = fminf(fmaxf(pcy - 0.5f * ph, 0.0f), 1.0f);
        float x2 = fminf(fmaxf(pcx + 0.5f * pw, 0.0f), 1.0f);
        float y2 = fminf(fmaxf(pcy + 0.5f * ph, 0.0f), 1.0f);

        float* bo = out + OFF_BOXES + (size_t)wid * 4;
        bo[0] = x1; bo[1] = y1; bo[2] = x2; bo[3] = y2;

        float w = x2 - x1, h = y2 - y1;
        int valid = (ms > 0.5f) && (w > 0.01f) && (h > 0.01f) &&
                    (w < 0.99f) && (h < 0.99f);
        g_valid[b][n] = valid;

        u32 ksb = ~__float_as_uint(ms);
        g_keys[b][n] = ((u64)ksb << 32) | (u32)n;
    }
}

/* ------------------------------------------------------------------ */
/* Kernel 2: bitonic sort of 8192 packed keys per batch                */
extern __shared__ u64 s_keys[];
__global__ void sort_kernel()
{
    int b = blockIdx.x;
    for (int i = threadIdx.x; i < NN; i += blockDim.x)
        s_keys[i] = g_keys[b][i];
    __syncthreads();

    for (int k = 2; k <= NN; k <<= 1) {
        for (int j = k >> 1; j > 0; j >>= 1) {
            for (int i = threadIdx.x; i < NN; i += blockDim.x) {
                int ixj = i ^ j;
                if (ixj > i) {
                    u64 a = s_keys[i];
                    u64 c = s_keys[ixj];
                    bool up = ((i & k) == 0);
                    if (up ? (a > c) : (a < c)) { s_keys[i] = c; s_keys[ixj] = a; }
                }
            }
            __syncthreads();
        }
    }
    for (int i = threadIdx.x; i < NN; i += blockDim.x)
        g_sorted[b][i] = (u32)(s_keys[i] & 0xffffffffull);
}

/* ------------------------------------------------------------------ */
/* Kernel 3: suppression bitmask; linearized upper-triangle tiles.     */
/* Writes TRANSPOSED layout g_maskT[b][cb][row] (coalesced).           */
__global__ void mask_kernel(const float* __restrict__ out)
{
    int b = blockIdx.y;
    int L = blockIdx.x;
    int cb = (int)((sqrtf(8.0f * (float)L + 1.0f) - 1.0f) * 0.5f);
    while ((cb + 1) * (cb + 2) / 2 <= L) cb++;
    while (cb * (cb + 1) / 2 > L) cb--;
    int rb = L - cb * (cb + 1) / 2;     /* rb <= cb */

    int t = threadIdx.x;  /* 64 threads */

    __shared__ float sx1[64], sy1[64], sx2[64], sy2[64], sar[64];
    __shared__ u64 srow[64];

    int cj = cb * 64 + t;
    u32 jidx = g_sorted[b][cj];
    float4 cbx = *(const float4*)(out + OFF_BOXES + ((size_t)b * NN + jidx) * 4);
    sx1[t] = cbx.x; sy1[t] = cbx.y; sx2[t] = cbx.z; sy2[t] = cbx.w;
    sar[t] = (cbx.z - cbx.x) * (cbx.w - cbx.y);
    __syncthreads();

    int i = rb * 64 + t;
    u32 iidx = g_sorted[b][i];
    float4 rbx = *(const float4*)(out + OFF_BOXES + ((size_t)b * NN + iidx) * 4);
    float ar = (rbx.z - rbx.x) * (rbx.w - rbx.y);

    u64 m = 0;
#pragma unroll 8
    for (int j = 0; j < 64; j++) {
        float ix1 = fmaxf(rbx.x, sx1[j]);
        float iy1 = fmaxf(rbx.y, sy1[j]);
        float ix2 = fminf(rbx.z, sx2[j]);
        float iy2 = fminf(rbx.w, sy2[j]);
        float iw = fmaxf(ix2 - ix1, 0.0f);
        float ih = fmaxf(iy2 - iy1, 0.0f);
        float inter = iw * ih;
        float uni = ar + sar[j] - inter;
        if (inter > 0.5f * fmaxf(uni, 1e-9f)) m |= 1ull << j;
    }
    if (cb == rb) m &= ~(1ull << t);
    g_maskT[b][cb][i] = m;             /* transposed, coalesced */

    if (cb == rb) {
        srow[t] = m;
        __syncthreads();
        u64 ct = 0;
#pragma unroll 8
        for (int j = 0; j < 64; j++)
            ct |= ((srow[j] >> t) & 1ull) << j;
        g_diagT[b][rb][t] = ct;
    }
}

/* ------------------------------------------------------------------ */
/* Kernel 4: pipelined greedy gather. 1 block/batch, 1024 threads.     */
/* Phase c: warp0 resolves chunk c  ||  warps1-31 OR chunk c-1 rows    */
/* into words [c+1..127] (transposed, coalesced, shfl-combined);       */
/* then warp0 ORs chunk c rows into word c+1 from a PREFETCHED smem    */
/* strip (prefetch distance 1 phase, by warp 1).                       */
__global__ __launch_bounds__(1024, 1)
void gather_kernel(float* __restrict__ out)
{
    extern __shared__ u64 sm[];
    u64* colTall = sm;                    /* NW*64 = 8192 u64 (64 KB)  */
    u64* removed = colTall + NW * 64;     /* NW                         */
    u64* keepw   = removed + NW;          /* NW                         */
    u64* sbuf    = keepw + NW;            /* 2*64 strip double buffer   */
    u32* vw32    = (u32*)(sbuf + 2 * 64); /* 2*NW u32                   */
    int* krows   = (int*)(vw32 + 2 * NW); /* 2*64 local kept indices    */
    __shared__ int kcnt_s[2];

    int b = blockIdx.x;
    int t = threadIdx.x;
    int lane = t & 31;
    int wrp  = t >> 5;

    for (int i = t; i < NW * 64; i += 1024)
        colTall[i] = g_diagT[b][0][i];
    if (t < NW) { removed[t] = 0ull; keepw[t] = 0ull; }
    if (t < 64) sbuf[t] = g_maskT[b][1][t];        /* strip for phase 0 stepB */
    if (t == 0) { kcnt_s[0] = 0; kcnt_s[1] = 0; }

    for (int p = 0; p < NN; p += 1024) {
        int i = p + t;
        u32 si = g_sorted[b][i];
        int v = g_valid[b][si];
        u32 bal = __ballot_sync(0xffffffffu, v != 0);
        if (lane == 0) vw32[i >> 5] = bal;
    }
    __syncthreads();

    for (int c = 0; c < NW; c++) {
        int pb = c & 1, qb = pb ^ 1;

        /* ---- STEP A (concurrent) ---- */
        if (wrp == 0) {
            /* resolve chunk c: ballot fixed point */
            u64 veff = (((u64)vw32[2 * c + 1] << 32) | (u64)vw32[2 * c])
                       & ~removed[c];
            u64 ct_lo = colTall[c * 64 + lane];
            u64 ct_hi = colTall[c * 64 + 32 + lane];
            u64 blo = (1ull << lane) - 1;
            u64 bhi = ((lane + 32) == 63) ? 0x7fffffffffffffffull
                                          : ((1ull << (lane + 32)) - 1);
            bool v0 = (veff >> lane) & 1;
            bool v1 = (veff >> (lane + 32)) & 1;

            u64 k = veff;
            for (int it = 0; it < 70; it++) {
                bool c0 = v0 && ((ct_lo & k & blo) == 0);
                bool c1 = v1 && ((ct_hi & k & bhi) == 0);
                u32 lo = __ballot_sync(0xffffffffu, c0);
                u32 hi = __ballot_sync(0xffffffffu, c1);
                u64 kn = (u64)lo | ((u64)hi << 32);
                if (kn == k) break;
                k = kn;
            }

            if ((k >> lane) & 1)
                krows[pb * 64 + __popcll(k & blo)] = lane;
            if ((k >> (lane + 32)) & 1)
                krows[pb * 64 + __popcll(k & bhi)] = lane + 32;
            if (lane == 0) { keepw[c] = k; kcnt_s[pb] = __popcll(k); }
        } else {
            if (wrp == 1 && c + 2 < NW) {
                /* prefetch strip for next phase's stepB */
                const u64* src = &g_maskT[b][c + 2][(c + 1) * 64];
                sbuf[qb * 64 + lane]      = src[lane];
                sbuf[qb * 64 + lane + 32] = src[lane + 32];
            }
            /* wide OR: chunk c-1 kept rows into words [c+1..127] */
            int cp = kcnt_s[qb];
            int R = NW - 1 - c;
            if (cp > 0 && R > 0) {
                int ns = 992 / R;
                int nsub = 1;
                while ((nsub << 1) <= ns && nsub < 16) nsub <<= 1;
                int tt = t - 32;
                int sub = tt & (nsub - 1);
                int wi  = tt / nsub;
                bool ok = wi < R;
                int w = c + 1 + wi;
                int base = (c - 1) * 64;
                const u64* col = ok ? &g_maskT[b][w][0] : 0;
                u64 r = 0;
                if (ok)
                    for (int q = sub; q < cp; q += nsub)
                        r |= col[base + krows[qb * 64 + q]];
                for (int off = nsub >> 1; off; off >>= 1)
                    r |= __shfl_xor_sync(0xffffffffu, r, off);
                if (ok && sub == 0 && r) removed[w] |= r;
            }
        }
        __syncthreads();

        /* ---- STEP B: chunk c kept rows into word c+1 (smem strip) ---- */
        if (wrp == 0 && c + 1 < NW) {
            int cnt = kcnt_s[pb];
            u64 r = 0;
            for (int q = lane; q < cnt; q += 32)
                r |= sbuf[pb * 64 + krows[pb * 64 + q]];
            for (int off = 16; off; off >>= 1)
                r |= __shfl_xor_sync(0xffffffffu, r, off);
            if (lane == 0 && r) removed[c + 1] |= r;
        }
        __syncthreads();
    }

    /* scatter keep back to original order */
    for (int i = t; i < NN; i += 1024) {
        u32 si = g_sorted[b][i];
        float kv = (float)((keepw[i >> 6] >> (i & 63)) & 1ull);
        out[OFF_KEEP + b * NN + si] = kv;
    }
}

/* ------------------------------------------------------------------ */
extern "C" void kernel_launch(void* const* d_in, const int* in_sizes, int n_in,
                              void* d_out, int out_size)
{
    (void)in_sizes; (void)n_in; (void)out_size;
    const float* logits  = (const float*)d_in[0];
    const float* deltas  = (const float*)d_in[1];
    const float* anchors = (const float*)d_in[2];
    float* out = (float*)d_out;

    cudaFuncSetAttribute(sort_kernel,
                         cudaFuncAttributeMaxDynamicSharedMemorySize,
                         NN * (int)sizeof(u64));
    int gsmem = (NW * 64 + 2 * NW + 2 * 64) * (int)sizeof(u64)
              + 2 * NW * (int)sizeof(u32) + 2 * 64 * (int)sizeof(int) + 256;
    cudaFuncSetAttribute(gather_kernel,
                         cudaFuncAttributeMaxDynamicSharedMemorySize, gsmem);

    prep_kernel<<<(BB * NN * 32 + 255) / 256, 256>>>(logits, deltas, anchors, out);
    sort_kernel<<<BB, 1024, NN * sizeof(u64)>>>();
    {
        dim3 grid(NW * (NW + 1) / 2, BB);
        mask_kernel<<<grid, 64>>>(out);
    }
    gather_kernel<<<BB, 1024, gsmem>>>(out);
}